// round 7
// baseline (speedup 1.0000x reference)
#include <cuda_runtime.h>
#include <cstdint>

#define NB 2
#define NN 50000
#define NF 128
#define NE 500000

// ---------------- scratch ----------------
__device__ int g_cnt[NN];      // zero at module load; re-zeroed by k_scan each call
__device__ int g_off[NN + 1];
__device__ int g_cur[NN];
__device__ int g_elist[NE];
// tf32-preconverted weight chunks: [6][128 cols][64 k]
// chunks 0-3: w0 k=0,64,128,192 ; chunks 4-5: w1 k=0,64
__device__ float g_wc[6][128][64];

// ---------------- tf32 helpers ----------------
__device__ __forceinline__ uint32_t f2tf(float f) {
    uint32_t r;
    asm("cvt.rna.tf32.f32 %0, %1;" : "=r"(r) : "f"(f));
    return r;
}
__device__ __forceinline__ float f2tff(float f) { return __uint_as_float(f2tf(f)); }
__device__ __forceinline__ float4 tf4(float4 v) {
    float4 c;
    c.x = f2tff(v.x); c.y = f2tff(v.y); c.z = f2tff(v.z); c.w = f2tff(v.w);
    return c;
}

// ---------------- kernel 0: weight preconvert ----------------
__global__ void k_wconv(const float* __restrict__ w0, const float* __restrict__ w1) {
    int i = blockIdx.x * blockDim.x + threadIdx.x;   // 6*128*64 = 49152
    if (i >= 6 * 128 * 64) return;
    int ch = i / (128 * 64);
    int col = (i >> 6) & 127;
    int k = i & 63;
    float v;
    if (ch < 4) v = w0[col * 256 + ch * 64 + k];
    else        v = w1[col * 128 + (ch - 4) * 64 + k];
    g_wc[ch][col][k] = f2tff(v);
}

// ---------------- kernel 1: degree histogram ----------------
__global__ void k_hist(const int* __restrict__ dst) {
    int e = blockIdx.x * blockDim.x + threadIdx.x;
    if (e < NE) atomicAdd(&g_cnt[dst[e]], 1);
}

// ---------------- kernel 2: exclusive scan + re-zero g_cnt ----------------
__global__ void k_scan() {
    __shared__ int part[1024];
    int t = threadIdx.x;
    const int CH = (NN + 1023) / 1024;
    int lo = t * CH;
    int hi = lo + CH; if (hi > NN) hi = NN;
    int s = 0;
    for (int i = lo; i < hi; i++) s += g_cnt[i];
    part[t] = s;
    __syncthreads();
    for (int d = 1; d < 1024; d <<= 1) {
        int v = (t >= d) ? part[t - d] : 0;
        __syncthreads();
        part[t] += v;
        __syncthreads();
    }
    int run = (t == 0) ? 0 : part[t - 1];
    for (int i = lo; i < hi; i++) {
        int c = g_cnt[i];
        g_off[i] = run;
        g_cur[i] = run;
        run += c;
        g_cnt[i] = 0;
    }
    if (t == 1023) g_off[NN] = part[1023];
}

// ---------------- kernel 3: CSR fill ----------------
__global__ void k_fill(const int* __restrict__ dst, const int* __restrict__ src) {
    int e = blockIdx.x * blockDim.x + threadIdx.x;
    if (e < NE) {
        int d = dst[e];
        int p = atomicAdd(&g_cur[d], 1);
        g_elist[p] = src[e];
    }
}

// ---------------- cp.async helpers ----------------
__device__ __forceinline__ void cp16(uint32_t saddr, const void* g) {
    asm volatile("cp.async.cg.shared.global [%0], [%1], 16;" :: "r"(saddr), "l"(g));
}
#define CP_COMMIT() asm volatile("cp.async.commit_group;" ::: "memory")
#define CP_WAIT0()  asm volatile("cp.async.wait_group 0;" ::: "memory")

// ---------------- kernel 4: fused reduce + tf32 MMA MLP ----------------
#define ROWS 128
#define NODES_PER_BLK 64
#define STRA 260           // xs row stride (conflict-free)
#define STRH 132           // hs row stride
#define STRW 68            // weight chunk row stride (K=64): (4c+k)%32 perm -> conflict-free
#define XS_FLOATS (ROWS * STRA)          // 33280
#define WBUF_FLOATS (128 * STRW)         // 8704 per buffer
#define WB0_OFF XS_FLOATS
#define WB1_OFF (XS_FLOATS + WBUF_FLOATS)
#define SM_FLOATS (XS_FLOATS + 2 * WBUF_FLOATS)   // 50688 floats = 202752 B

__device__ __forceinline__ void mma8(float d[4],
                                     uint32_t a0, uint32_t a1, uint32_t a2, uint32_t a3,
                                     uint32_t b0, uint32_t b1) {
    asm volatile(
        "mma.sync.aligned.m16n8k8.row.col.f32.tf32.tf32.f32 "
        "{%0,%1,%2,%3}, {%4,%5,%6,%7}, {%8,%9}, {%0,%1,%2,%3};\n"
        : "+f"(d[0]), "+f"(d[1]), "+f"(d[2]), "+f"(d[3])
        : "r"(a0), "r"(a1), "r"(a2), "r"(a3), "r"(b0), "r"(b1));
}

__global__ __launch_bounds__(512, 1)
void k_main(const float* __restrict__ x0,
            const float* __restrict__ b0v,
            const float* __restrict__ b1v, float* __restrict__ out) {
    extern __shared__ float sm[];
    float* xs = sm;                 // [128][STRA] A tile (later hs)
    float* hs = sm;                 // h tile [128][STRH] reuses xs region

    const int t = threadIdx.x;
    const int warp = t >> 5;
    const int lane = t & 31;
    const int gid = lane >> 2;
    const int tig = lane & 3;
    const int node0 = blockIdx.x * NODES_PER_BLK;

    float* wbuf[2] = { sm + WB0_OFF, sm + WB1_OFF };

    // ---- stage chunk 0 via cp.async (completes during gather) ----
    // 128 rows x 64 floats = 2048 float4; 4 per thread
    {
        uint32_t sa = (uint32_t)__cvta_generic_to_shared(wbuf[0]);
        for (int i = t; i < 2048; i += 512) {
            int row = i >> 4, q = i & 15;
            cp16(sa + (uint32_t)(row * STRW + q * 4) * 4, &g_wc[0][row][q * 4]);
        }
        CP_COMMIT();
    }

    // ======== phase 1: gather + segment mean/max into xs (tf32) ========
    const float NEG_INF = __int_as_float(0xff800000);
    #pragma unroll
    for (int nn = 0; nn < 4; nn++) {
        int ln = warp * 4 + nn;
        int n = node0 + ln;
        float4 s0 = make_float4(0.f, 0.f, 0.f, 0.f), s1 = s0;
        float4 m0 = make_float4(NEG_INF, NEG_INF, NEG_INF, NEG_INF), m1 = m0;
        int deg = 0;
        if (n < NN) {
            int beg = g_off[n], end = g_off[n + 1];
            deg = end - beg;
            int ei = beg;
            int idx[4];
            #pragma unroll
            for (int j = 0; j < 4; j++) idx[j] = (beg + j < end) ? g_elist[beg + j] : 0;
            while (ei < end) {
                int nxt[4];
                #pragma unroll
                for (int j = 0; j < 4; j++)
                    nxt[j] = (ei + 4 + j < end) ? g_elist[ei + 4 + j] : 0;
                #pragma unroll
                for (int j = 0; j < 4; j++) {
                    if (ei + j < end) {
                        float4 v0 = ((const float4*)x0)[idx[j] * 32 + lane];
                        float4 v1 = ((const float4*)x0)[NN * 32 + idx[j] * 32 + lane];
                        s0.x += v0.x; s0.y += v0.y; s0.z += v0.z; s0.w += v0.w;
                        s1.x += v1.x; s1.y += v1.y; s1.z += v1.z; s1.w += v1.w;
                        m0.x = fmaxf(m0.x, v0.x); m0.y = fmaxf(m0.y, v0.y);
                        m0.z = fmaxf(m0.z, v0.z); m0.w = fmaxf(m0.w, v0.w);
                        m1.x = fmaxf(m1.x, v1.x); m1.y = fmaxf(m1.y, v1.y);
                        m1.z = fmaxf(m1.z, v1.z); m1.w = fmaxf(m1.w, v1.w);
                    }
                }
                #pragma unroll
                for (int j = 0; j < 4; j++) idx[j] = nxt[j];
                ei += 4;
            }
        }
        float* r0p = xs + (ln * 2 + 0) * STRA;
        float* r1p = xs + (ln * 2 + 1) * STRA;
        float4 mean0, mean1, amax0, amax1;
        if (n < NN && deg > 0) {
            float inv = 1.0f / (float)deg;
            mean0 = make_float4(s0.x * inv, s0.y * inv, s0.z * inv, s0.w * inv);
            mean1 = make_float4(s1.x * inv, s1.y * inv, s1.z * inv, s1.w * inv);
            amax0 = m0; amax1 = m1;
        } else if (n < NN) {
            float4 v0 = ((const float4*)x0)[n * 32 + lane];
            float4 v1 = ((const float4*)x0)[NN * 32 + n * 32 + lane];
            mean0 = v0; amax0 = v0;
            mean1 = v1; amax1 = v1;
        } else {
            float4 z = make_float4(0.f, 0.f, 0.f, 0.f);
            mean0 = z; mean1 = z; amax0 = z; amax1 = z;
        }
        ((float4*)r0p)[lane]         = tf4(mean0);
        ((float4*)(r0p + 128))[lane] = tf4(amax0);
        ((float4*)r1p)[lane]         = tf4(mean1);
        ((float4*)(r1p + 128))[lane] = tf4(amax1);
    }

    // ======== warp tile mapping ========
    const int rg = warp >> 2;
    const int cg = warp & 3;
    const int mr = rg * 32;
    const int nc = cg * 32;

    const uint32_t* xsu = (const uint32_t*)xs;

    // ======== GEMM1: chunks 0..3 (K=256), double-buffered weights ========
    float d1[2][4][4];
    #pragma unroll
    for (int j = 0; j < 4; j++) {
        int c0 = nc + 8 * j + 2 * tig;
        float bb0 = b0v[c0], bb1 = b0v[c0 + 1];
        #pragma unroll
        for (int mi = 0; mi < 2; mi++) {
            d1[mi][j][0] = bb0; d1[mi][j][1] = bb1;
            d1[mi][j][2] = bb0; d1[mi][j][3] = bb1;
        }
    }

    #pragma unroll
    for (int kc = 0; kc < 4; kc++) {
        CP_WAIT0();
        __syncthreads();                       // chunk kc visible; all warps done kc-1
        // prefetch chunk kc+1 into other buffer (overlaps this chunk's MMAs)
        {
            uint32_t sa = (uint32_t)__cvta_generic_to_shared(wbuf[(kc + 1) & 1]);
            for (int i = t; i < 2048; i += 512) {
                int row = i >> 4, q = i & 15;
                cp16(sa + (uint32_t)(row * STRW + q * 4) * 4, &g_wc[kc + 1][row][q * 4]);
            }
            CP_COMMIT();
        }
        const uint32_t* wbu = (const uint32_t*)wbuf[kc & 1];
        #pragma unroll
        for (int ks = 0; ks < 8; ks++) {
            int kk = kc * 64 + ks * 8;
            int kl = ks * 8;
            uint32_t a[2][4], b[4][2];
            #pragma unroll
            for (int mi = 0; mi < 2; mi++) {
                int r0 = mr + mi * 16 + gid;
                a[mi][0] = xsu[r0 * STRA + kk + tig];
                a[mi][1] = xsu[(r0 + 8) * STRA + kk + tig];
                a[mi][2] = xsu[r0 * STRA + kk + tig + 4];
                a[mi][3] = xsu[(r0 + 8) * STRA + kk + tig + 4];
            }
            #pragma unroll
            for (int j = 0; j < 4; j++) {
                int c = nc + 8 * j + gid;
                b[j][0] = wbu[c * STRW + kl + tig];
                b[j][1] = wbu[c * STRW + kl + tig + 4];
            }
            #pragma unroll
            for (int mi = 0; mi < 2; mi++)
                #pragma unroll
                for (int j = 0; j < 4; j++)
                    mma8(d1[mi][j], a[mi][0], a[mi][1], a[mi][2], a[mi][3],
                         b[j][0], b[j][1]);
        }
    }

    __syncthreads();   // all warps done reading xs (chunk3 MMAs)

    // store relu(h) as tf32 into hs
    #pragma unroll
    for (int mi = 0; mi < 2; mi++) {
        #pragma unroll
        for (int j = 0; j < 4; j++) {
            int r0 = mr + mi * 16 + gid;
            int c0 = nc + 8 * j + 2 * tig;
            hs[r0 * STRH + c0]           = f2tff(fmaxf(d1[mi][j][0], 0.f));
            hs[r0 * STRH + c0 + 1]       = f2tff(fmaxf(d1[mi][j][1], 0.f));
            hs[(r0 + 8) * STRH + c0]     = f2tff(fmaxf(d1[mi][j][2], 0.f));
            hs[(r0 + 8) * STRH + c0 + 1] = f2tff(fmaxf(d1[mi][j][3], 0.f));
        }
    }

    // ======== GEMM2: chunks 4..5 (w1, K=128) ========
    float d2[2][4][4];
    #pragma unroll
    for (int j = 0; j < 4; j++) {
        int c0 = nc + 8 * j + 2 * tig;
        float bb0 = b1v[c0], bb1 = b1v[c0 + 1];
        #pragma unroll
        for (int mi = 0; mi < 2; mi++) {
            d2[mi][j][0] = bb0; d2[mi][j][1] = bb1;
            d2[mi][j][2] = bb0; d2[mi][j][3] = bb1;
        }
    }
    const uint32_t* hsu = (const uint32_t*)hs;

    #pragma unroll
    for (int kc = 4; kc < 6; kc++) {
        CP_WAIT0();
        __syncthreads();                 // chunk kc visible; hs visible (kc=4); kc-1 reads done
        if (kc < 5) {
            uint32_t sa = (uint32_t)__cvta_generic_to_shared(wbuf[(kc + 1) & 1]);
            for (int i = t; i < 2048; i += 512) {
                int row = i >> 4, q = i & 15;
                cp16(sa + (uint32_t)(row * STRW + q * 4) * 4, &g_wc[kc + 1][row][q * 4]);
            }
            CP_COMMIT();
        }
        const uint32_t* wbu = (const uint32_t*)wbuf[kc & 1];
        #pragma unroll
        for (int ks = 0; ks < 8; ks++) {
            int kk = (kc - 4) * 64 + ks * 8;
            int kl = ks * 8;
            uint32_t a[2][4], b[4][2];
            #pragma unroll
            for (int mi = 0; mi < 2; mi++) {
                int r0 = mr + mi * 16 + gid;
                a[mi][0] = hsu[r0 * STRH + kk + tig];
                a[mi][1] = hsu[(r0 + 8) * STRH + kk + tig];
                a[mi][2] = hsu[r0 * STRH + kk + tig + 4];
                a[mi][3] = hsu[(r0 + 8) * STRH + kk + tig + 4];
            }
            #pragma unroll
            for (int j = 0; j < 4; j++) {
                int c = nc + 8 * j + gid;
                b[j][0] = wbu[c * STRW + kl + tig];
                b[j][1] = wbu[c * STRW + kl + tig + 4];
            }
            #pragma unroll
            for (int mi = 0; mi < 2; mi++)
                #pragma unroll
                for (int j = 0; j < 4; j++)
                    mma8(d2[mi][j], a[mi][0], a[mi][1], a[mi][2], a[mi][3],
                         b[j][0], b[j][1]);
        }
    }

    // ======== epilogue: residual + store ========
    #pragma unroll
    for (int mi = 0; mi < 2; mi++) {
        #pragma unroll
        for (int j = 0; j < 4; j++) {
            int c0 = nc + 8 * j + 2 * tig;
            #pragma unroll
            for (int h = 0; h < 2; h++) {
                int r = mr + mi * 16 + gid + h * 8;
                int n = node0 + (r >> 1);
                if (n < NN) {
                    int b = r & 1;
                    int base = b * NN * NF + n * NF + c0;
                    float2 xv = *(const float2*)(x0 + base);
                    float2 o;
                    o.x = xv.x + d2[mi][j][h * 2 + 0];
                    o.y = xv.y + d2[mi][j][h * 2 + 1];
                    *(float2*)(out + base) = o;
                }
            }
        }
    }
}

// ---------------- launcher ----------------
extern "C" void kernel_launch(void* const* d_in, const int* in_sizes, int n_in,
                              void* d_out, int out_size) {
    const float* x0  = (const float*)d_in[0];
    const int*   dst = (const int*)d_in[1];
    const int*   src = (const int*)d_in[2];
    const float* w0  = (const float*)d_in[3];
    const float* b0  = (const float*)d_in[4];
    const float* w1  = (const float*)d_in[5];
    const float* b1  = (const float*)d_in[6];
    float* out = (float*)d_out;

    cudaFuncSetAttribute(k_main, cudaFuncAttributeMaxDynamicSharedMemorySize,
                         SM_FLOATS * (int)sizeof(float));

    k_wconv<<<(6 * 128 * 64 + 255) / 256, 256>>>(w0, w1);
    k_hist<<<(NE + 255) / 256, 256>>>(dst);
    k_scan<<<1, 1024>>>();
    k_fill<<<(NE + 255) / 256, 256>>>(dst, src);

    int tiles = (NN + NODES_PER_BLK - 1) / NODES_PER_BLK;   // 782
    k_main<<<tiles, 512, SM_FLOATS * (int)sizeof(float)>>>(x0, b0, b1, out);
}

// round 8
// speedup vs baseline: 1.0981x; 1.0981x over previous
#include <cuda_runtime.h>
#include <cstdint>

#define NB 2
#define NN 50000
#define NF 128
#define NE 500000

// ---------------- scratch ----------------
__device__ int g_cnt[NN];      // zero at module load; re-zeroed by k_scan each call
__device__ int g_off[NN + 1];
__device__ int g_cur[NN];
__device__ int g_elist[NE];

// ---------------- kernel 1: degree histogram (g_cnt pre-zeroed) ----------------
__global__ void k_hist(const int* __restrict__ dst) {
    int e = blockIdx.x * blockDim.x + threadIdx.x;
    if (e < NE) atomicAdd(&g_cnt[dst[e]], 1);
}

// ---------------- kernel 2: exclusive scan (single block) + re-zero g_cnt ----------------
__global__ void k_scan() {
    __shared__ int part[1024];
    int t = threadIdx.x;
    const int CH = (NN + 1023) / 1024;
    int lo = t * CH;
    int hi = lo + CH; if (hi > NN) hi = NN;
    int s = 0;
    for (int i = lo; i < hi; i++) s += g_cnt[i];
    part[t] = s;
    __syncthreads();
    for (int d = 1; d < 1024; d <<= 1) {
        int v = (t >= d) ? part[t - d] : 0;
        __syncthreads();
        part[t] += v;
        __syncthreads();
    }
    int run = (t == 0) ? 0 : part[t - 1];
    for (int i = lo; i < hi; i++) {
        int c = g_cnt[i];
        g_off[i] = run;
        g_cur[i] = run;
        run += c;
        g_cnt[i] = 0;          // restore invariant for next launch call
    }
    if (t == 1023) g_off[NN] = part[1023];
}

// ---------------- kernel 3: CSR fill ----------------
__global__ void k_fill(const int* __restrict__ dst, const int* __restrict__ src) {
    int e = blockIdx.x * blockDim.x + threadIdx.x;
    if (e < NE) {
        int d = dst[e];
        int p = atomicAdd(&g_cur[d], 1);
        g_elist[p] = src[e];
    }
}

// ---------------- kernel 4: fused reduce + tf32 MMA MLP (1024 threads) ----------------
#define THREADS 1024
#define ROWS 128           // 64 nodes * B(2)
#define NODES_PER_BLK 64
#define STRA 260           // A row stride: (r*260+k)%32 == (r*4+k)%32 -> conflict-free
#define STRB 132           // weight/h row stride
#define XS_FLOATS (ROWS * STRA)     // 33280
#define WB_FLOATS (128 * STRB)      // 16896
#define SM_FLOATS (XS_FLOATS + WB_FLOATS)   // 50176 floats = 200704 B

__device__ __forceinline__ uint32_t f2tf(float f) {
    uint32_t r;
    asm("cvt.rna.tf32.f32 %0, %1;" : "=r"(r) : "f"(f));
    return r;
}
__device__ __forceinline__ float f2tff(float f) { return __uint_as_float(f2tf(f)); }
__device__ __forceinline__ float4 tf4(float4 v) {
    float4 c;
    c.x = f2tff(v.x); c.y = f2tff(v.y); c.z = f2tff(v.z); c.w = f2tff(v.w);
    return c;
}

__device__ __forceinline__ void mma8(float d[4],
                                     uint32_t a0, uint32_t a1, uint32_t a2, uint32_t a3,
                                     uint32_t b0, uint32_t b1) {
    asm volatile(
        "mma.sync.aligned.m16n8k8.row.col.f32.tf32.tf32.f32 "
        "{%0,%1,%2,%3}, {%4,%5,%6,%7}, {%8,%9}, {%0,%1,%2,%3};\n"
        : "+f"(d[0]), "+f"(d[1]), "+f"(d[2]), "+f"(d[3])
        : "r"(a0), "r"(a1), "r"(a2), "r"(a3), "r"(b0), "r"(b1));
}

__global__ __launch_bounds__(THREADS, 1)
void k_main(const float* __restrict__ x0, const float* __restrict__ w0,
            const float* __restrict__ b0v, const float* __restrict__ w1,
            const float* __restrict__ b1v, float* __restrict__ out) {
    extern __shared__ float sm[];
    float* xs = sm;                 // [128][STRA] A tile (tf32 bits)
    float* wb = sm + XS_FLOATS;     // [128][STRB] weight chunk
    float* hs = sm;                 // h tile reuses xs region after GEMM1

    const int t = threadIdx.x;
    const int warp = t >> 5;        // 0..31
    const int lane = t & 31;
    const int gid = lane >> 2;      // 0..7
    const int tig = lane & 3;       // 0..3
    const int node0 = blockIdx.x * NODES_PER_BLK;

    // ======== phase 1: gather + segment mean/max into xs (tf32) ========
    // each of 32 warps reduces 2 nodes (R2-style simple loop: let ptxas pipeline it)
    const float NEG_INF = __int_as_float(0xff800000);
    #pragma unroll
    for (int nn = 0; nn < 2; nn++) {
        int ln = warp * 2 + nn;         // local node 0..63
        int n = node0 + ln;
        float4 s0 = make_float4(0.f, 0.f, 0.f, 0.f), s1 = s0;
        float4 m0 = make_float4(NEG_INF, NEG_INF, NEG_INF, NEG_INF), m1 = m0;
        int deg = 0;
        if (n < NN) {
            int beg = g_off[n], end = g_off[n + 1];
            deg = end - beg;
            for (int ei = beg; ei < end; ei++) {
                int sidx = g_elist[ei];
                float4 v0 = ((const float4*)x0)[sidx * 32 + lane];
                float4 v1 = ((const float4*)x0)[NN * 32 + sidx * 32 + lane];
                s0.x += v0.x; s0.y += v0.y; s0.z += v0.z; s0.w += v0.w;
                s1.x += v1.x; s1.y += v1.y; s1.z += v1.z; s1.w += v1.w;
                m0.x = fmaxf(m0.x, v0.x); m0.y = fmaxf(m0.y, v0.y);
                m0.z = fmaxf(m0.z, v0.z); m0.w = fmaxf(m0.w, v0.w);
                m1.x = fmaxf(m1.x, v1.x); m1.y = fmaxf(m1.y, v1.y);
                m1.z = fmaxf(m1.z, v1.z); m1.w = fmaxf(m1.w, v1.w);
            }
        }
        float* r0p = xs + (ln * 2 + 0) * STRA;
        float* r1p = xs + (ln * 2 + 1) * STRA;
        float4 mean0, mean1, amax0, amax1;
        if (n < NN && deg > 0) {
            float inv = 1.0f / (float)deg;
            mean0 = make_float4(s0.x * inv, s0.y * inv, s0.z * inv, s0.w * inv);
            mean1 = make_float4(s1.x * inv, s1.y * inv, s1.z * inv, s1.w * inv);
            amax0 = m0; amax1 = m1;
        } else if (n < NN) {
            float4 v0 = ((const float4*)x0)[n * 32 + lane];
            float4 v1 = ((const float4*)x0)[NN * 32 + n * 32 + lane];
            mean0 = v0; amax0 = v0;
            mean1 = v1; amax1 = v1;
        } else {
            float4 z = make_float4(0.f, 0.f, 0.f, 0.f);
            mean0 = z; mean1 = z; amax0 = z; amax1 = z;
        }
        ((float4*)r0p)[lane]         = tf4(mean0);
        ((float4*)(r0p + 128))[lane] = tf4(amax0);
        ((float4*)r1p)[lane]         = tf4(mean1);
        ((float4*)(r1p + 128))[lane] = tf4(amax1);
    }

    // ======== warp tile mapping: 32 rows x 16 cols (32 warps = 4x8 grid) ========
    const int rg = warp >> 3;          // 0..3
    const int cg = warp & 7;           // 0..7
    const int mr = rg * 32;
    const int nc = cg * 16;

    // ======== GEMM1: h = relu(x @ w0^T + b0), K=256 in 2 chunks ========
    float d1[2][2][4];
    #pragma unroll
    for (int j = 0; j < 2; j++) {
        int c0 = nc + 8 * j + 2 * tig;
        float bb0 = b0v[c0], bb1 = b0v[c0 + 1];
        #pragma unroll
        for (int mi = 0; mi < 2; mi++) {
            d1[mi][j][0] = bb0; d1[mi][j][1] = bb1;
            d1[mi][j][2] = bb0; d1[mi][j][3] = bb1;
        }
    }

    const uint32_t* xsu = (const uint32_t*)xs;
    const uint32_t* wbu = (const uint32_t*)wb;

    #pragma unroll
    for (int kc = 0; kc < 2; kc++) {
        __syncthreads();
        // stage w0 chunk [128 out][128 k] -> wb (tf32-rounded)
        for (int i = t; i < 128 * 32; i += THREADS) {
            int col = i >> 5;
            int q = i & 31;
            float4 v = ((const float4*)(w0 + col * 256 + kc * 128))[q];
            *(float4*)(wb + col * STRB + q * 4) = tf4(v);
        }
        __syncthreads();

        #pragma unroll 4
        for (int ks = 0; ks < 16; ks++) {
            int kk = kc * 128 + ks * 8;
            uint32_t a[2][4], b[2][2];
            #pragma unroll
            for (int mi = 0; mi < 2; mi++) {
                int r0 = mr + mi * 16 + gid;
                a[mi][0] = xsu[r0 * STRA + kk + tig];
                a[mi][1] = xsu[(r0 + 8) * STRA + kk + tig];
                a[mi][2] = xsu[r0 * STRA + kk + tig + 4];
                a[mi][3] = xsu[(r0 + 8) * STRA + kk + tig + 4];
            }
            #pragma unroll
            for (int j = 0; j < 2; j++) {
                int c = nc + 8 * j + gid;
                b[j][0] = wbu[c * STRB + ks * 8 + tig];
                b[j][1] = wbu[c * STRB + ks * 8 + tig + 4];
            }
            #pragma unroll
            for (int mi = 0; mi < 2; mi++)
                #pragma unroll
                for (int j = 0; j < 2; j++)
                    mma8(d1[mi][j], a[mi][0], a[mi][1], a[mi][2], a[mi][3],
                         b[j][0], b[j][1]);
        }
    }

    __syncthreads();   // xs and wb fully consumed

    // store relu(h) as tf32 into hs[row][k] (stride STRB); also stage w1 into wb
    #pragma unroll
    for (int mi = 0; mi < 2; mi++) {
        #pragma unroll
        for (int j = 0; j < 2; j++) {
            int r0 = mr + mi * 16 + gid;
            int c0 = nc + 8 * j + 2 * tig;
            hs[r0 * STRB + c0]           = f2tff(fmaxf(d1[mi][j][0], 0.f));
            hs[r0 * STRB + c0 + 1]       = f2tff(fmaxf(d1[mi][j][1], 0.f));
            hs[(r0 + 8) * STRB + c0]     = f2tff(fmaxf(d1[mi][j][2], 0.f));
            hs[(r0 + 8) * STRB + c0 + 1] = f2tff(fmaxf(d1[mi][j][3], 0.f));
        }
    }
    for (int i = t; i < 128 * 32; i += THREADS) {
        int col = i >> 5;
        int q = i & 31;
        float4 v = ((const float4*)(w1 + col * 128))[q];
        *(float4*)(wb + col * STRB + q * 4) = tf4(v);
    }
    __syncthreads();

    // ======== GEMM2: out = x0 + h @ w1^T + b1, K=128 ========
    float d2[2][2][4];
    #pragma unroll
    for (int j = 0; j < 2; j++) {
        int c0 = nc + 8 * j + 2 * tig;
        float bb0 = b1v[c0], bb1 = b1v[c0 + 1];
        #pragma unroll
        for (int mi = 0; mi < 2; mi++) {
            d2[mi][j][0] = bb0; d2[mi][j][1] = bb1;
            d2[mi][j][2] = bb0; d2[mi][j][3] = bb1;
        }
    }
    const uint32_t* hsu = (const uint32_t*)hs;

    #pragma unroll 4
    for (int ks = 0; ks < 16; ks++) {
        int kk = ks * 8;
        uint32_t a[2][4], b[2][2];
        #pragma unroll
        for (int mi = 0; mi < 2; mi++) {
            int r0 = mr + mi * 16 + gid;
            a[mi][0] = hsu[r0 * STRB + kk + tig];
            a[mi][1] = hsu[(r0 + 8) * STRB + kk + tig];
            a[mi][2] = hsu[r0 * STRB + kk + tig + 4];
            a[mi][3] = hsu[(r0 + 8) * STRB + kk + tig + 4];
        }
        #pragma unroll
        for (int j = 0; j < 2; j++) {
            int c = nc + 8 * j + gid;
            b[j][0] = wbu[c * STRB + kk + tig];
            b[j][1] = wbu[c * STRB + kk + tig + 4];
        }
        #pragma unroll
        for (int mi = 0; mi < 2; mi++)
            #pragma unroll
            for (int j = 0; j < 2; j++)
                mma8(d2[mi][j], a[mi][0], a[mi][1], a[mi][2], a[mi][3],
                     b[j][0], b[j][1]);
    }

    // ======== epilogue: residual + store ========
    #pragma unroll
    for (int mi = 0; mi < 2; mi++) {
        #pragma unroll
        for (int j = 0; j < 2; j++) {
            int c0 = nc + 8 * j + 2 * tig;
            #pragma unroll
            for (int h = 0; h < 2; h++) {
                int r = mr + mi * 16 + gid + h * 8;
                int n = node0 + (r >> 1);
                if (n < NN) {
                    int b = r & 1;
                    int base = b * NN * NF + n * NF + c0;
                    float2 xv = *(const float2*)(x0 + base);
                    float2 o;
                    o.x = xv.x + d2[mi][j][h * 2 + 0];
                    o.y = xv.y + d2[mi][j][h * 2 + 1];
                    *(float2*)(out + base) = o;
                }
            }
        }
    }
}

// ---------------- launcher ----------------
extern "C" void kernel_launch(void* const* d_in, const int* in_sizes, int n_in,
                              void* d_out, int out_size) {
    const float* x0  = (const float*)d_in[0];
    const int*   dst = (const int*)d_in[1];
    const int*   src = (const int*)d_in[2];
    const float* w0  = (const float*)d_in[3];
    const float* b0  = (const float*)d_in[4];
    const float* w1  = (const float*)d_in[5];
    const float* b1  = (const float*)d_in[6];
    float* out = (float*)d_out;

    cudaFuncSetAttribute(k_main, cudaFuncAttributeMaxDynamicSharedMemorySize,
                         SM_FLOATS * (int)sizeof(float));

    k_hist<<<(NE + 255) / 256, 256>>>(dst);
    k_scan<<<1, 1024>>>();
    k_fill<<<(NE + 255) / 256, 256>>>(dst, src);

    int tiles = (NN + NODES_PER_BLK - 1) / NODES_PER_BLK;   // 782
    k_main<<<tiles, THREADS, SM_FLOATS * (int)sizeof(float)>>>(x0, w0, b0, w1, b1, out);
}

// round 9
// speedup vs baseline: 1.6375x; 1.4913x over previous
#include <cuda_runtime.h>
#include <cstdint>

#define NB 2
#define NN 50000
#define NF 128
#define NE 500000
#define SCAN_BLKS ((NN + 255) / 256)   // 196

// ---------------- scratch ----------------
__device__ int g_cnt[NN];      // zero at module load; re-zeroed by k_scan3 each call
__device__ int g_off[NN + 1];
__device__ int g_cur[NN];
__device__ int g_elist[NE];
__device__ int g_bsum[SCAN_BLKS];
__device__ int g_boff[SCAN_BLKS];

// ---------------- kernel 1: degree histogram (g_cnt pre-zeroed) ----------------
__global__ void k_hist(const int* __restrict__ dst) {
    int e = blockIdx.x * blockDim.x + threadIdx.x;
    if (e < NE) atomicAdd(&g_cnt[dst[e]], 1);
}

// ---------------- scan stage 1: per-block partial sums ----------------
__global__ void k_scan1() {
    __shared__ int red[256];
    int t = threadIdx.x;
    int i = blockIdx.x * 256 + t;
    int v = (i < NN) ? g_cnt[i] : 0;
    red[t] = v;
    __syncthreads();
    #pragma unroll
    for (int d = 128; d > 0; d >>= 1) {
        if (t < d) red[t] += red[t + d];
        __syncthreads();
    }
    if (t == 0) g_bsum[blockIdx.x] = red[0];
}

// ---------------- scan stage 2: scan of block sums (1 small block) ----------------
__global__ void k_scan2() {
    __shared__ int s[256];
    int t = threadIdx.x;
    int v = (t < SCAN_BLKS) ? g_bsum[t] : 0;
    s[t] = v;
    __syncthreads();
    #pragma unroll
    for (int d = 1; d < 256; d <<= 1) {
        int u = (t >= d) ? s[t - d] : 0;
        __syncthreads();
        s[t] += u;
        __syncthreads();
    }
    if (t < SCAN_BLKS) g_boff[t] = s[t] - v;   // exclusive
    if (t == 255) g_off[NN] = s[255];          // total = NE
}

// ---------------- scan stage 3: apply offsets, write g_off/g_cur, re-zero g_cnt ----------------
__global__ void k_scan3() {
    __shared__ int s[256];
    int t = threadIdx.x;
    int i = blockIdx.x * 256 + t;
    int v = (i < NN) ? g_cnt[i] : 0;
    s[t] = v;
    __syncthreads();
    #pragma unroll
    for (int d = 1; d < 256; d <<= 1) {
        int u = (t >= d) ? s[t - d] : 0;
        __syncthreads();
        s[t] += u;
        __syncthreads();
    }
    if (i < NN) {
        int off = g_boff[blockIdx.x] + s[t] - v;   // exclusive prefix
        g_off[i] = off;
        g_cur[i] = off;
        g_cnt[i] = 0;                              // restore invariant
    }
}

// ---------------- kernel 3: CSR fill ----------------
__global__ void k_fill(const int* __restrict__ dst, const int* __restrict__ src) {
    int e = blockIdx.x * blockDim.x + threadIdx.x;
    if (e < NE) {
        int d = dst[e];
        int p = atomicAdd(&g_cur[d], 1);
        g_elist[p] = src[e];
    }
}

// ---------------- kernel 4: fused reduce + tf32 MMA MLP (1024 threads) ----------------
#define THREADS 1024
#define ROWS 128           // 64 nodes * B(2)
#define NODES_PER_BLK 64
#define STRA 260           // A row stride: (r*260+k)%32 == (r*4+k)%32 -> conflict-free
#define STRB 132           // weight/h row stride
#define XS_FLOATS (ROWS * STRA)     // 33280
#define WB_FLOATS (128 * STRB)      // 16896
#define SM_FLOATS (XS_FLOATS + WB_FLOATS)   // 50176 floats = 200704 B

__device__ __forceinline__ uint32_t f2tf(float f) {
    uint32_t r;
    asm("cvt.rna.tf32.f32 %0, %1;" : "=r"(r) : "f"(f));
    return r;
}
__device__ __forceinline__ float f2tff(float f) { return __uint_as_float(f2tf(f)); }
__device__ __forceinline__ float4 tf4(float4 v) {
    float4 c;
    c.x = f2tff(v.x); c.y = f2tff(v.y); c.z = f2tff(v.z); c.w = f2tff(v.w);
    return c;
}

__device__ __forceinline__ void mma8(float d[4],
                                     uint32_t a0, uint32_t a1, uint32_t a2, uint32_t a3,
                                     uint32_t b0, uint32_t b1) {
    asm volatile(
        "mma.sync.aligned.m16n8k8.row.col.f32.tf32.tf32.f32 "
        "{%0,%1,%2,%3}, {%4,%5,%6,%7}, {%8,%9}, {%0,%1,%2,%3};\n"
        : "+f"(d[0]), "+f"(d[1]), "+f"(d[2]), "+f"(d[3])
        : "r"(a0), "r"(a1), "r"(a2), "r"(a3), "r"(b0), "r"(b1));
}

__global__ __launch_bounds__(THREADS, 1)
void k_main(const float* __restrict__ x0, const float* __restrict__ w0,
            const float* __restrict__ b0v, const float* __restrict__ w1,
            const float* __restrict__ b1v, float* __restrict__ out) {
    extern __shared__ float sm[];
    float* xs = sm;                 // [128][STRA] A tile (tf32 bits)
    float* wb = sm + XS_FLOATS;     // [128][STRB] weight chunk
    float* hs = sm;                 // h tile reuses xs region after GEMM1

    const int t = threadIdx.x;
    const int warp = t >> 5;        // 0..31
    const int lane = t & 31;
    const int gid = lane >> 2;      // 0..7
    const int tig = lane & 3;       // 0..3
    const int node0 = blockIdx.x * NODES_PER_BLK;

    // ======== phase 1: gather + segment mean/max into xs (tf32) ========
    const float NEG_INF = __int_as_float(0xff800000);
    #pragma unroll
    for (int nn = 0; nn < 2; nn++) {
        int ln = warp * 2 + nn;         // local node 0..63
        int n = node0 + ln;
        float4 s0 = make_float4(0.f, 0.f, 0.f, 0.f), s1 = s0;
        float4 m0 = make_float4(NEG_INF, NEG_INF, NEG_INF, NEG_INF), m1 = m0;
        int deg = 0;
        if (n < NN) {
            int beg = g_off[n], end = g_off[n + 1];
            deg = end - beg;
            for (int ei = beg; ei < end; ei++) {
                int sidx = g_elist[ei];
                float4 v0 = ((const float4*)x0)[sidx * 32 + lane];
                float4 v1 = ((const float4*)x0)[NN * 32 + sidx * 32 + lane];
                s0.x += v0.x; s0.y += v0.y; s0.z += v0.z; s0.w += v0.w;
                s1.x += v1.x; s1.y += v1.y; s1.z += v1.z; s1.w += v1.w;
                m0.x = fmaxf(m0.x, v0.x); m0.y = fmaxf(m0.y, v0.y);
                m0.z = fmaxf(m0.z, v0.z); m0.w = fmaxf(m0.w, v0.w);
                m1.x = fmaxf(m1.x, v1.x); m1.y = fmaxf(m1.y, v1.y);
                m1.z = fmaxf(m1.z, v1.z); m1.w = fmaxf(m1.w, v1.w);
            }
        }
        float* r0p = xs + (ln * 2 + 0) * STRA;
        float* r1p = xs + (ln * 2 + 1) * STRA;
        float4 mean0, mean1, amax0, amax1;
        if (n < NN && deg > 0) {
            float inv = 1.0f / (float)deg;
            mean0 = make_float4(s0.x * inv, s0.y * inv, s0.z * inv, s0.w * inv);
            mean1 = make_float4(s1.x * inv, s1.y * inv, s1.z * inv, s1.w * inv);
            amax0 = m0; amax1 = m1;
        } else if (n < NN) {
            float4 v0 = ((const float4*)x0)[n * 32 + lane];
            float4 v1 = ((const float4*)x0)[NN * 32 + n * 32 + lane];
            mean0 = v0; amax0 = v0;
            mean1 = v1; amax1 = v1;
        } else {
            float4 z = make_float4(0.f, 0.f, 0.f, 0.f);
            mean0 = z; mean1 = z; amax0 = z; amax1 = z;
        }
        ((float4*)r0p)[lane]         = tf4(mean0);
        ((float4*)(r0p + 128))[lane] = tf4(amax0);
        ((float4*)r1p)[lane]         = tf4(mean1);
        ((float4*)(r1p + 128))[lane] = tf4(amax1);
    }

    // ======== warp tile mapping: 32 rows x 16 cols (32 warps = 4x8 grid) ========
    const int rg = warp >> 3;          // 0..3
    const int cg = warp & 7;           // 0..7
    const int mr = rg * 32;
    const int nc = cg * 16;

    // ======== GEMM1: h = relu(x @ w0^T + b0), K=256 in 2 chunks ========
    float d1[2][2][4];
    #pragma unroll
    for (int j = 0; j < 2; j++) {
        int c0 = nc + 8 * j + 2 * tig;
        float bb0 = b0v[c0], bb1 = b0v[c0 + 1];
        #pragma unroll
        for (int mi = 0; mi < 2; mi++) {
            d1[mi][j][0] = bb0; d1[mi][j][1] = bb1;
            d1[mi][j][2] = bb0; d1[mi][j][3] = bb1;
        }
    }

    const uint32_t* xsu = (const uint32_t*)xs;
    const uint32_t* wbu = (const uint32_t*)wb;

    #pragma unroll
    for (int kc = 0; kc < 2; kc++) {
        __syncthreads();
        for (int i = t; i < 128 * 32; i += THREADS) {
            int col = i >> 5;
            int q = i & 31;
            float4 v = ((const float4*)(w0 + col * 256 + kc * 128))[q];
            *(float4*)(wb + col * STRB + q * 4) = tf4(v);
        }
        __syncthreads();

        #pragma unroll 4
        for (int ks = 0; ks < 16; ks++) {
            int kk = kc * 128 + ks * 8;
            uint32_t a[2][4], b[2][2];
            #pragma unroll
            for (int mi = 0; mi < 2; mi++) {
                int r0 = mr + mi * 16 + gid;
                a[mi][0] = xsu[r0 * STRA + kk + tig];
                a[mi][1] = xsu[(r0 + 8) * STRA + kk + tig];
                a[mi][2] = xsu[r0 * STRA + kk + tig + 4];
                a[mi][3] = xsu[(r0 + 8) * STRA + kk + tig + 4];
            }
            #pragma unroll
            for (int j = 0; j < 2; j++) {
                int c = nc + 8 * j + gid;
                b[j][0] = wbu[c * STRB + ks * 8 + tig];
                b[j][1] = wbu[c * STRB + ks * 8 + tig + 4];
            }
            #pragma unroll
            for (int mi = 0; mi < 2; mi++)
                #pragma unroll
                for (int j = 0; j < 2; j++)
                    mma8(d1[mi][j], a[mi][0], a[mi][1], a[mi][2], a[mi][3],
                         b[j][0], b[j][1]);
        }
    }

    __syncthreads();   // xs and wb fully consumed

    // store relu(h) as tf32 into hs[row][k] (stride STRB); also stage w1 into wb
    #pragma unroll
    for (int mi = 0; mi < 2; mi++) {
        #pragma unroll
        for (int j = 0; j < 2; j++) {
            int r0 = mr + mi * 16 + gid;
            int c0 = nc + 8 * j + 2 * tig;
            hs[r0 * STRB + c0]           = f2tff(fmaxf(d1[mi][j][0], 0.f));
            hs[r0 * STRB + c0 + 1]       = f2tff(fmaxf(d1[mi][j][1], 0.f));
            hs[(r0 + 8) * STRB + c0]     = f2tff(fmaxf(d1[mi][j][2], 0.f));
            hs[(r0 + 8) * STRB + c0 + 1] = f2tff(fmaxf(d1[mi][j][3], 0.f));
        }
    }
    for (int i = t; i < 128 * 32; i += THREADS) {
        int col = i >> 5;
        int q = i & 31;
        float4 v = ((const float4*)(w1 + col * 128))[q];
        *(float4*)(wb + col * STRB + q * 4) = tf4(v);
    }
    __syncthreads();

    // ======== GEMM2: out = x0 + h @ w1^T + b1, K=128 ========
    float d2[2][2][4];
    #pragma unroll
    for (int j = 0; j < 2; j++) {
        int c0 = nc + 8 * j + 2 * tig;
        float bb0 = b1v[c0], bb1 = b1v[c0 + 1];
        #pragma unroll
        for (int mi = 0; mi < 2; mi++) {
            d2[mi][j][0] = bb0; d2[mi][j][1] = bb1;
            d2[mi][j][2] = bb0; d2[mi][j][3] = bb1;
        }
    }
    const uint32_t* hsu = (const uint32_t*)hs;

    #pragma unroll 4
    for (int ks = 0; ks < 16; ks++) {
        int kk = ks * 8;
        uint32_t a[2][4], b[2][2];
        #pragma unroll
        for (int mi = 0; mi < 2; mi++) {
            int r0 = mr + mi * 16 + gid;
            a[mi][0] = hsu[r0 * STRB + kk + tig];
            a[mi][1] = hsu[(r0 + 8) * STRB + kk + tig];
            a[mi][2] = hsu[r0 * STRB + kk + tig + 4];
            a[mi][3] = hsu[(r0 + 8) * STRB + kk + tig + 4];
        }
        #pragma unroll
        for (int j = 0; j < 2; j++) {
            int c = nc + 8 * j + gid;
            b[j][0] = wbu[c * STRB + kk + tig];
            b[j][1] = wbu[c * STRB + kk + tig + 4];
        }
        #pragma unroll
        for (int mi = 0; mi < 2; mi++)
            #pragma unroll
            for (int j = 0; j < 2; j++)
                mma8(d2[mi][j], a[mi][0], a[mi][1], a[mi][2], a[mi][3],
                     b[j][0], b[j][1]);
    }

    // ======== epilogue: residual + store ========
    #pragma unroll
    for (int mi = 0; mi < 2; mi++) {
        #pragma unroll
        for (int j = 0; j < 2; j++) {
            int c0 = nc + 8 * j + 2 * tig;
            #pragma unroll
            for (int h = 0; h < 2; h++) {
                int r = mr + mi * 16 + gid + h * 8;
                int n = node0 + (r >> 1);
                if (n < NN) {
                    int b = r & 1;
                    int base = b * NN * NF + n * NF + c0;
                    float2 xv = *(const float2*)(x0 + base);
                    float2 o;
                    o.x = xv.x + d2[mi][j][h * 2 + 0];
                    o.y = xv.y + d2[mi][j][h * 2 + 1];
                    *(float2*)(out + base) = o;
                }
            }
        }
    }
}

// ---------------- launcher ----------------
extern "C" void kernel_launch(void* const* d_in, const int* in_sizes, int n_in,
                              void* d_out, int out_size) {
    const float* x0  = (const float*)d_in[0];
    const int*   dst = (const int*)d_in[1];
    const int*   src = (const int*)d_in[2];
    const float* w0  = (const float*)d_in[3];
    const float* b0  = (const float*)d_in[4];
    const float* w1  = (const float*)d_in[5];
    const float* b1  = (const float*)d_in[6];
    float* out = (float*)d_out;

    cudaFuncSetAttribute(k_main, cudaFuncAttributeMaxDynamicSharedMemorySize,
                         SM_FLOATS * (int)sizeof(float));

    k_hist<<<(NE + 255) / 256, 256>>>(dst);
    k_scan1<<<SCAN_BLKS, 256>>>();
    k_scan2<<<1, 256>>>();
    k_scan3<<<SCAN_BLKS, 256>>>();
    k_fill<<<(NE + 255) / 256, 256>>>(dst, src);

    int tiles = (NN + NODES_PER_BLK - 1) / NODES_PER_BLK;   // 782
    k_main<<<tiles, THREADS, SM_FLOATS * (int)sizeof(float)>>>(x0, w0, b0, w1, b1, out);
}